// round 1
// baseline (speedup 1.0000x reference)
#include <cuda_runtime.h>

// ---------------- tile config ----------------
#define BM 128
#define BN 128
#define BK 16
#define TM 8
#define TN 8
#define NT 256   // threads per block

// ---------------- problem dims ----------------
#define BATCH 4
#define SEQ   2048
#define DIM   1024
#define BT    (BATCH*SEQ)          // 8192

// ---------------- scratch (no allocs allowed) ----------------
__device__ float g_Q[BATCH*SEQ*DIM];
__device__ float g_K[BATCH*SEQ*DIM];
__device__ float g_V[BATCH*SEQ*DIM];
__device__ float g_S[(long)BATCH*SEQ*SEQ];

// ============================================================
// Generic 128x128x16 SGEMM tile body.
// A: [M,K] row-major. If BNT: B is [N,K] row-major (C = A*B^T).
// else: B is [K,N] row-major (C = A*B).  C: [M,N] row-major.
// blockIdx.x -> N tile, blockIdx.y -> M tile. All dims multiples of tile.
// ============================================================
template<bool BNT>
__device__ __forceinline__ void gemm_tile(const float* __restrict__ A,
                                          const float* __restrict__ B,
                                          float* __restrict__ C,
                                          int N, int K, float alpha)
{
    __shared__ float As[BK*BM];
    __shared__ float Bs[BK*BN];

    const int tid = threadIdx.x;
    const int tx  = tid & 15;   // 0..15 (N dir)
    const int ty  = tid >> 4;   // 0..15 (M dir)
    const int m0  = blockIdx.y * BM;
    const int n0  = blockIdx.x * BN;

    float acc[TM][TN];
#pragma unroll
    for (int i = 0; i < TM; ++i)
#pragma unroll
        for (int j = 0; j < TN; ++j) acc[i][j] = 0.f;

    for (int k0 = 0; k0 < K; k0 += BK) {
        // ---- load A tile (128 rows x 16 cols), store transposed As[k][m]
#pragma unroll
        for (int i = 0; i < 2; ++i) {
            int idx = tid + i * NT;        // 0..511 float4 slots
            int r   = idx >> 2;            // 0..127
            int c4  = idx & 3;             // 0..3
            float4 v = *(const float4*)&A[(long)(m0 + r) * K + k0 + c4 * 4];
            As[(c4*4+0)*BM + r] = v.x;
            As[(c4*4+1)*BM + r] = v.y;
            As[(c4*4+2)*BM + r] = v.z;
            As[(c4*4+3)*BM + r] = v.w;
        }
        // ---- load B tile
        if (BNT) {
            // B[N,K]: 128 rows x 16 cols, transposed into Bs[k][n]
#pragma unroll
            for (int i = 0; i < 2; ++i) {
                int idx = tid + i * NT;
                int r   = idx >> 2;
                int c4  = idx & 3;
                float4 v = *(const float4*)&B[(long)(n0 + r) * K + k0 + c4 * 4];
                Bs[(c4*4+0)*BN + r] = v.x;
                Bs[(c4*4+1)*BN + r] = v.y;
                Bs[(c4*4+2)*BN + r] = v.z;
                Bs[(c4*4+3)*BN + r] = v.w;
            }
        } else {
            // B[K,N]: 16 rows x 128 cols, direct copy Bs[k][n]
#pragma unroll
            for (int i = 0; i < 2; ++i) {
                int idx = tid + i * NT;    // 0..511
                int kr  = idx >> 5;        // 0..15
                int c4  = idx & 31;        // 0..31
                *(float4*)&Bs[kr*BN + c4*4] =
                    *(const float4*)&B[(long)(k0 + kr) * N + n0 + c4 * 4];
            }
        }
        __syncthreads();

        // ---- 8x8 microtile FMAs
#pragma unroll
        for (int kk = 0; kk < BK; ++kk) {
            float ra[TM], rb[TN];
#pragma unroll
            for (int i = 0; i < TM; ++i) ra[i] = As[kk*BM + ty*TM + i];
#pragma unroll
            for (int j = 0; j < TN; ++j) rb[j] = Bs[kk*BN + tx*TN + j];
#pragma unroll
            for (int i = 0; i < TM; ++i)
#pragma unroll
                for (int j = 0; j < TN; ++j)
                    acc[i][j] += ra[i] * rb[j];
        }
        __syncthreads();
    }

    // ---- epilogue (vectorized, scaled)
#pragma unroll
    for (int i = 0; i < TM; ++i) {
        long row = m0 + ty*TM + i;
#pragma unroll
        for (int j = 0; j < TN; j += 4) {
            float4 v;
            v.x = acc[i][j+0] * alpha;
            v.y = acc[i][j+1] * alpha;
            v.z = acc[i][j+2] * alpha;
            v.w = acc[i][j+3] * alpha;
            *(float4*)&C[row * N + n0 + tx*TN + j] = v;
        }
    }
}

// ============================================================
// Kernels
// ============================================================

// QKV projections: [8192,1024] @ W^T, W is [out,in]=[1024,1024] -> NT GEMM.
// grid = (1024/BN, 8192/BM, 3); z selects Q/K/V.
__global__ __launch_bounds__(NT, 2)
void qkv_kernel(const float* __restrict__ x,
                const float* __restrict__ Wq,
                const float* __restrict__ Wk,
                const float* __restrict__ Wv)
{
    const float* W = (blockIdx.z == 0) ? Wq : (blockIdx.z == 1) ? Wk : Wv;
    float*       C = (blockIdx.z == 0) ? g_Q : (blockIdx.z == 1) ? g_K : g_V;
    gemm_tile<true>(x, W, C, DIM, DIM, 1.0f);
}

// S = Q K^T / sqrt(D), per batch (grid.z). NT GEMM, M=N=2048, K=1024.
__global__ __launch_bounds__(NT, 2)
void scores_kernel()
{
    long z = blockIdx.z;
    gemm_tile<true>(g_Q + z * (long)SEQ * DIM,
                    g_K + z * (long)SEQ * DIM,
                    g_S + z * (long)SEQ * SEQ,
                    SEQ, DIM, 0.03125f /* 1/sqrt(1024) */);
}

// Row softmax over S (in place). One block per row, 256 threads, float4.
__global__ __launch_bounds__(NT)
void softmax_kernel()
{
    long row = blockIdx.x;                   // 0 .. BATCH*SEQ-1
    float4* p = (float4*)(g_S + row * (long)SEQ);
    const int n4 = SEQ / 4;                  // 512
    int tid = threadIdx.x;
    __shared__ float red[NT];

    // max
    float m = -1e30f;
    for (int i = tid; i < n4; i += NT) {
        float4 v = p[i];
        m = fmaxf(m, fmaxf(fmaxf(v.x, v.y), fmaxf(v.z, v.w)));
    }
    red[tid] = m; __syncthreads();
    for (int s = NT/2; s > 0; s >>= 1) {
        if (tid < s) red[tid] = fmaxf(red[tid], red[tid + s]);
        __syncthreads();
    }
    m = red[0]; __syncthreads();

    // exp + sum
    float sum = 0.f;
    for (int i = tid; i < n4; i += NT) {
        float4 v = p[i];
        v.x = __expf(v.x - m); v.y = __expf(v.y - m);
        v.z = __expf(v.z - m); v.w = __expf(v.w - m);
        p[i] = v;
        sum += v.x + v.y + v.z + v.w;
    }
    red[tid] = sum; __syncthreads();
    for (int s = NT/2; s > 0; s >>= 1) {
        if (tid < s) red[tid] += red[tid + s];
        __syncthreads();
    }
    float inv = 1.f / red[0];

    // normalize
    for (int i = tid; i < n4; i += NT) {
        float4 v = p[i];
        v.x *= inv; v.y *= inv; v.z *= inv; v.w *= inv;
        p[i] = v;
    }
}

// O = P V per batch. NN GEMM: P [2048,2048] @ V [2048,1024].
__global__ __launch_bounds__(NT, 2)
void out_kernel(float* __restrict__ out)
{
    long z = blockIdx.z;
    gemm_tile<false>(g_S + z * (long)SEQ * SEQ,
                     g_V + z * (long)SEQ * DIM,
                     out + z * (long)SEQ * DIM,
                     DIM, SEQ, 1.0f);
}

// ============================================================
// Launch
// ============================================================
extern "C" void kernel_launch(void* const* d_in, const int* in_sizes, int n_in,
                              void* d_out, int out_size)
{
    const float* x  = (const float*)d_in[0];
    const float* Wq = (const float*)d_in[1];
    const float* Wk = (const float*)d_in[2];
    const float* Wv = (const float*)d_in[3];
    float* out = (float*)d_out;

    dim3 blk(NT);

    dim3 g_qkv(DIM / BN, BT / BM, 3);        // (8, 64, 3)
    qkv_kernel<<<g_qkv, blk>>>(x, Wq, Wk, Wv);

    dim3 g_sc(SEQ / BN, SEQ / BM, BATCH);    // (16, 16, 4)
    scores_kernel<<<g_sc, blk>>>();

    softmax_kernel<<<BT, blk>>>();           // 8192 rows

    dim3 g_out(DIM / BN, SEQ / BM, BATCH);   // (8, 16, 4)
    out_kernel<<<g_out, blk>>>(out);
}

// round 5
// speedup vs baseline: 3.2150x; 3.2150x over previous
#include <cuda_runtime.h>
#include <cstdint>

// ---------------- problem dims ----------------
#define BATCH 4
#define SEQ   2048
#define DIM   1024
#define BT    (BATCH*SEQ)          // 8192

// ---------------- tile config ----------------
#define BM 128
#define BN 128
#define BK 32
#define NT 256                     // 8 warps
#define SKA 36                     // A/B(NT) smem row stride ([row][k], pad 4)
#define SKB 132                    // B(NN) smem row stride ([k][n], pad 4)

// ---------------- scratch (no allocs allowed) ----------------
__device__ float g_Q[BATCH*SEQ*DIM];
__device__ float g_K[BATCH*SEQ*DIM];
__device__ float g_V[BATCH*SEQ*DIM];
__device__ float g_S[(long)BATCH*SEQ*SEQ];

// ---------------- tf32 helpers ----------------
__device__ __forceinline__ uint32_t f2tf(float f) {
    uint32_t u;
    asm("cvt.rna.tf32.f32 %0, %1;" : "=r"(u) : "f"(f));
    return u;
}

__device__ __forceinline__ void mma8(float* c,
                                     uint32_t a0, uint32_t a1, uint32_t a2, uint32_t a3,
                                     uint32_t b0, uint32_t b1)
{
    asm volatile(
        "mma.sync.aligned.m16n8k8.row.col.f32.tf32.tf32.f32 "
        "{%0,%1,%2,%3}, {%4,%5,%6,%7}, {%8,%9}, {%0,%1,%2,%3};"
        : "+f"(c[0]), "+f"(c[1]), "+f"(c[2]), "+f"(c[3])
        : "r"(a0), "r"(a1), "r"(a2), "r"(a3), "r"(b0), "r"(b1));
}

// ============================================================
// 128x128x32 TF32 tensor-core GEMM tile with LDG reg-prefetch.
// A: [M,K] row-major. BNT=true: B [N,K] row-major (C = A*B^T).
//                     BNT=false: B [K,N] row-major (C = A*B).
// C: [M,N] row-major. All dims multiples of tiles. alpha scales output.
// 8 warps laid out 2(M) x 4(N); warp tile 64x32 -> 4 m16 x 4 n8 MMAs.
// ============================================================
template<bool BNT>
__device__ __forceinline__ void gemm_tile(const float* __restrict__ A,
                                          const float* __restrict__ B,
                                          float* __restrict__ C,
                                          int N, int K, float alpha)
{
    __shared__ uint32_t As[BM * SKA];                       // [m][k]
    __shared__ uint32_t Bs[BNT ? (BN * SKA) : (BK * SKB)];  // NT: [n][k]; NN: [k][n]

    const int tid  = threadIdx.x;
    const int lane = tid & 31;
    const int warp = tid >> 5;
    const int wm   = warp >> 2;        // 0..1
    const int wn   = warp & 3;         // 0..3
    const int lr   = lane >> 2;        // 0..7
    const int lc   = lane & 3;         // 0..3
    const int m0   = blockIdx.y * BM;
    const int n0   = blockIdx.x * BN;

    float acc[4][4][4];
#pragma unroll
    for (int i = 0; i < 4; ++i)
#pragma unroll
        for (int j = 0; j < 4; ++j)
#pragma unroll
            for (int e = 0; e < 4; ++e) acc[i][j][e] = 0.f;

    float4 pfA[4], pfB[4];

    // ---- prologue: LDG tile k0=0 into registers
    {
        const float* Ab = A + (long)m0 * K;
#pragma unroll
        for (int i = 0; i < 4; ++i) {
            int idx = tid + i * NT;
            int r   = idx >> 3;
            int c4  = idx & 7;
            pfA[i] = *(const float4*)(Ab + (long)r * K + c4 * 4);
        }
        if (BNT) {
            const float* Bb = B + (long)n0 * K;
#pragma unroll
            for (int i = 0; i < 4; ++i) {
                int idx = tid + i * NT;
                int r   = idx >> 3;
                int c4  = idx & 7;
                pfB[i] = *(const float4*)(Bb + (long)r * K + c4 * 4);
            }
        } else {
            const float* Bb = B + n0;
#pragma unroll
            for (int i = 0; i < 4; ++i) {
                int idx = tid + i * NT;
                int kr  = idx >> 5;
                int c4  = idx & 31;
                pfB[i] = *(const float4*)(Bb + (long)kr * N + c4 * 4);
            }
        }
    }

    for (int k0 = 0; k0 < K; k0 += BK) {
        // ---- STS staged registers (convert to tf32)
#pragma unroll
        for (int i = 0; i < 4; ++i) {
            int idx = tid + i * NT;
            int r   = idx >> 3;
            int c4  = idx & 7;
            uint32_t* s = &As[r * SKA + c4 * 4];
            s[0] = f2tf(pfA[i].x); s[1] = f2tf(pfA[i].y);
            s[2] = f2tf(pfA[i].z); s[3] = f2tf(pfA[i].w);
        }
        if (BNT) {
#pragma unroll
            for (int i = 0; i < 4; ++i) {
                int idx = tid + i * NT;
                int r   = idx >> 3;
                int c4  = idx & 7;
                uint32_t* s = &Bs[r * SKA + c4 * 4];
                s[0] = f2tf(pfB[i].x); s[1] = f2tf(pfB[i].y);
                s[2] = f2tf(pfB[i].z); s[3] = f2tf(pfB[i].w);
            }
        } else {
#pragma unroll
            for (int i = 0; i < 4; ++i) {
                int idx = tid + i * NT;
                int kr  = idx >> 5;
                int c4  = idx & 31;
                uint32_t* s = &Bs[kr * SKB + c4 * 4];
                s[0] = f2tf(pfB[i].x); s[1] = f2tf(pfB[i].y);
                s[2] = f2tf(pfB[i].z); s[3] = f2tf(pfB[i].w);
            }
        }
        __syncthreads();

        // ---- prefetch next tile (overlaps with MMAs below)
        if (k0 + BK < K) {
            const float* Ab = A + (long)m0 * K + (k0 + BK);
#pragma unroll
            for (int i = 0; i < 4; ++i) {
                int idx = tid + i * NT;
                int r   = idx >> 3;
                int c4  = idx & 7;
                pfA[i] = *(const float4*)(Ab + (long)r * K + c4 * 4);
            }
            if (BNT) {
                const float* Bb = B + (long)n0 * K + (k0 + BK);
#pragma unroll
                for (int i = 0; i < 4; ++i) {
                    int idx = tid + i * NT;
                    int r   = idx >> 3;
                    int c4  = idx & 7;
                    pfB[i] = *(const float4*)(Bb + (long)r * K + c4 * 4);
                }
            } else {
                const float* Bb = B + (long)(k0 + BK) * N + n0;
#pragma unroll
                for (int i = 0; i < 4; ++i) {
                    int idx = tid + i * NT;
                    int kr  = idx >> 5;
                    int c4  = idx & 31;
                    pfB[i] = *(const float4*)(Bb + (long)kr * N + c4 * 4);
                }
            }
        }

        // ---- 4 k8-steps of MMAs
#pragma unroll
        for (int ks = 0; ks < BK; ks += 8) {
            uint32_t af[4][4];
#pragma unroll
            for (int mt = 0; mt < 4; ++mt) {
                int r = wm * 64 + mt * 16 + lr;
                const uint32_t* p = &As[r * SKA + ks + lc];
                af[mt][0] = p[0];
                af[mt][1] = p[8 * SKA];
                af[mt][2] = p[4];
                af[mt][3] = p[8 * SKA + 4];
            }
            uint32_t bf[4][2];
            if (BNT) {
#pragma unroll
                for (int nt = 0; nt < 4; ++nt) {
                    int n = wn * 32 + nt * 8 + lr;
                    const uint32_t* p = &Bs[n * SKA + ks + lc];
                    bf[nt][0] = p[0];
                    bf[nt][1] = p[4];
                }
            } else {
#pragma unroll
                for (int nt = 0; nt < 4; ++nt) {
                    const uint32_t* p = &Bs[(ks + lc) * SKB + wn * 32 + nt * 8 + lr];
                    bf[nt][0] = p[0];
                    bf[nt][1] = p[4 * SKB];
                }
            }
#pragma unroll
            for (int mt = 0; mt < 4; ++mt)
#pragma unroll
                for (int nt = 0; nt < 4; ++nt)
                    mma8(acc[mt][nt],
                         af[mt][0], af[mt][1], af[mt][2], af[mt][3],
                         bf[nt][0], bf[nt][1]);
        }
        __syncthreads();
    }

    // ---- epilogue: float2 stores, scaled
#pragma unroll
    for (int mt = 0; mt < 4; ++mt) {
#pragma unroll
        for (int nt = 0; nt < 4; ++nt) {
            int r = m0 + wm * 64 + mt * 16 + lr;
            int c = n0 + wn * 32 + nt * 8 + 2 * lc;
            float2 v0 = make_float2(acc[mt][nt][0] * alpha, acc[mt][nt][1] * alpha);
            float2 v1 = make_float2(acc[mt][nt][2] * alpha, acc[mt][nt][3] * alpha);
            *(float2*)&C[(long)r * N + c]       = v0;
            *(float2*)&C[(long)(r + 8) * N + c] = v1;
        }
    }
}

// ============================================================
// Kernels
// ============================================================

__global__ __launch_bounds__(NT, 2)
void qkv_kernel(const float* __restrict__ x,
                const float* __restrict__ Wq,
                const float* __restrict__ Wk,
                const float* __restrict__ Wv)
{
    const float* W = (blockIdx.z == 0) ? Wq : (blockIdx.z == 1) ? Wk : Wv;
    float*       C = (blockIdx.z == 0) ? g_Q : (blockIdx.z == 1) ? g_K : g_V;
    gemm_tile<true>(x, W, C, DIM, DIM, 1.0f);
}

__global__ __launch_bounds__(NT, 2)
void scores_kernel()
{
    long z = blockIdx.z;
    gemm_tile<true>(g_Q + z * (long)SEQ * DIM,
                    g_K + z * (long)SEQ * DIM,
                    g_S + z * (long)SEQ * SEQ,
                    SEQ, DIM, 0.03125f /* 1/sqrt(1024) */);
}

__global__ __launch_bounds__(NT)
void softmax_kernel()
{
    long row = blockIdx.x;
    float4* p = (float4*)(g_S + row * (long)SEQ);
    const int n4 = SEQ / 4;
    int tid = threadIdx.x;
    __shared__ float red[NT];

    float m = -1e30f;
    for (int i = tid; i < n4; i += NT) {
        float4 v = p[i];
        m = fmaxf(m, fmaxf(fmaxf(v.x, v.y), fmaxf(v.z, v.w)));
    }
    red[tid] = m; __syncthreads();
    for (int s = NT / 2; s > 0; s >>= 1) {
        if (tid < s) red[tid] = fmaxf(red[tid], red[tid + s]);
        __syncthreads();
    }
    m = red[0]; __syncthreads();

    float sum = 0.f;
    for (int i = tid; i < n4; i += NT) {
        float4 v = p[i];
        v.x = __expf(v.x - m); v.y = __expf(v.y - m);
        v.z = __expf(v.z - m); v.w = __expf(v.w - m);
        p[i] = v;
        sum += v.x + v.y + v.z + v.w;
    }
    red[tid] = sum; __syncthreads();
    for (int s = NT / 2; s > 0; s >>= 1) {
        if (tid < s) red[tid] += red[tid + s];
        __syncthreads();
    }
    float inv = 1.f / red[0];

    for (int i = tid; i < n4; i += NT) {
        float4 v = p[i];
        v.x *= inv; v.y *= inv; v.z *= inv; v.w *= inv;
        p[i] = v;
    }
}

__global__ __launch_bounds__(NT, 2)
void out_kernel(float* __restrict__ out)
{
    long z = blockIdx.z;
    gemm_tile<false>(g_S + z * (long)SEQ * SEQ,
                     g_V + z * (long)SEQ * DIM,
                     out + z * (long)SEQ * DIM,
                     DIM, SEQ, 1.0f);
}

// ============================================================
// Launch
// ============================================================
extern "C" void kernel_launch(void* const* d_in, const int* in_sizes, int n_in,
                              void* d_out, int out_size)
{
    const float* x  = (const float*)d_in[0];
    const float* Wq = (const float*)d_in[1];
    const float* Wk = (const float*)d_in[2];
    const float* Wv = (const float*)d_in[3];
    float* out = (float*)d_out;

    dim3 blk(NT);

    dim3 g_qkv(DIM / BN, BT / BM, 3);        // (8, 64, 3)
    qkv_kernel<<<g_qkv, blk>>>(x, Wq, Wk, Wv);

    dim3 g_sc(SEQ / BN, SEQ / BM, BATCH);    // (16, 16, 4)
    scores_kernel<<<g_sc, blk>>>();

    softmax_kernel<<<BT, blk>>>();           // 8192 rows

    dim3 g_out(DIM / BN, SEQ / BM, BATCH);   // (8, 16, 4)
    out_kernel<<<g_out, blk>>>(out);
}